// round 12
// baseline (speedup 1.0000x reference)
#include <cuda_runtime.h>
#include <math.h>

// Conv2dODENet dopri5 — persistent kernel. R12: ticket work-stealing
// (conv1 units + fused conv2/conv3 tiles), tree barrier, y-update folded
// into stage-0 conv1. Phase bodies are R10's (proven).
#define CC 64
#define FF 128
#define OUTC 10
#define NPIX 32768
#define NY (NPIX*CC)
#define NH (NPIX*FF)
#define GRIDN 296
#define NT 256
#define NITER 32
#define NU 256                    // units per steal phase
#define C2STR 276
#define C2BUF (16*C2STR)          // 4416
#define W2BUF 6144
#define SPOOL (C2BUF + 2*W2BUF)   // 16704 floats
#define SPOOL_BYTES (SPOOL*4)

typedef unsigned long long u64;

__device__ __forceinline__ u64 pk2(float x) {
  u64 r; asm("mov.b64 %0, {%1, %1};" : "=l"(r) : "r"(__float_as_uint(x))); return r;
}
__device__ __forceinline__ void fma2(u64 &d, u64 a, u64 b) {
  asm("fma.rn.f32x2 %0, %1, %2, %3;" : "=l"(d) : "l"(a), "l"(b), "l"(d));
}
__device__ __forceinline__ float2 up2(u64 v) {
  unsigned lo, hi;
  asm("mov.b64 {%0, %1}, %2;" : "=r"(lo), "=r"(hi) : "l"(v));
  return make_float2(__uint_as_float(lo), __uint_as_float(hi));
}
__device__ __forceinline__ void cpa16(float* dst, const float* src) {
  unsigned d = (unsigned)__cvta_generic_to_shared(dst);
  asm volatile("cp.async.cg.shared.global [%0], [%1], 16;" :: "r"(d), "l"(src));
}
#define CP_COMMIT() asm volatile("cp.async.commit_group;" ::: "memory")
#define CP_WAIT1()  asm volatile("cp.async.wait_group 1;" ::: "memory")
#define CP_WAIT0()  asm volatile("cp.async.wait_group 0;" ::: "memory")

// ----------------------------- device state --------------------------------
__device__ float g_y[NY];
__device__ float g_y5[NY];
__device__ float g_k[7][NY];
__device__ float g_h1[NH];
__device__ float g_h2[NH];
__device__ float g_S2[9*FF];
__device__ float g_partial[GRIDN];
__device__ float g_t, g_h, g_hs;
__device__ int   g_done, g_accept;
__device__ unsigned g_gen, g_sub[32], g_root, g_ticket;

__constant__ float c_comb[7][6] = {
  { 0,0,0,0,0,0 },
  { (float)(1.0/5.0), 0,0,0,0,0 },
  { (float)(3.0/40.0), (float)(9.0/40.0), 0,0,0,0 },
  { (float)(44.0/45.0), (float)(-56.0/15.0), (float)(32.0/9.0), 0,0,0 },
  { (float)(19372.0/6561.0), (float)(-25360.0/2187.0), (float)(64448.0/6561.0),
    (float)(-212.0/729.0), 0,0 },
  { (float)(9017.0/3168.0), (float)(-355.0/33.0), (float)(46732.0/5247.0),
    (float)(49.0/176.0), (float)(-5103.0/18656.0), 0 },
  { (float)(35.0/384.0), 0.0f, (float)(500.0/1113.0), (float)(125.0/192.0),
    (float)(-2187.0/6784.0), (float)(11.0/84.0) },
};
__constant__ float c_cs[7] = { 0.0f, (float)(1.0/5.0), (float)(3.0/10.0),
  (float)(4.0/5.0), (float)(8.0/9.0), 1.0f, 1.0f };

#define E1f ((float)(71.0/57600.0))
#define E3f ((float)(-71.0/16695.0))
#define E4f ((float)(71.0/1920.0))
#define E5f ((float)(-17253.0/339200.0))
#define E6f ((float)(22.0/525.0))
#define E7f ((float)(-1.0/40.0))
#define TOLf 1e-3f

// ----------------------------- tree grid barrier ---------------------------
__device__ __forceinline__ void gbar() {
  __syncthreads();
  if (threadIdx.x == 0) {
    __threadfence();
    unsigned gen = *(volatile unsigned*)&g_gen;
    int si = blockIdx.x & 31;
    unsigned cnt = (si < 8) ? 10u : 9u;          // 296 = 8*10 + 24*9
    if (atomicAdd(&g_sub[si], 1u) == cnt - 1u) {
      atomicExch(&g_sub[si], 0u);
      __threadfence();
      if (atomicAdd(&g_root, 1u) == 31u) {
        atomicExch(&g_root, 0u);
        __threadfence();
        *(volatile unsigned*)&g_gen = gen + 1u;
      }
    }
    while (*(volatile unsigned*)&g_gen == gen) { __nanosleep(32); }
    __threadfence();
  }
  __syncthreads();
}

// ----------------------------- work stealing -------------------------------
// Every block exits a phase on exactly one failing add: adds/phase = NU+GRIDN.
__device__ __forceinline__ int steal(unsigned base) {
  __shared__ unsigned s_tk;
  __syncthreads();
  if (threadIdx.x == 0) s_tk = atomicAdd(&g_ticket, 1u);
  __syncthreads();
  unsigned r = s_tk - base;
  return (r < (unsigned)NU) ? (int)r : -1;
}

// ----------------------------- conv1 unit: 128px, 1x1 65->128, ReLU --------
__device__ void conv1_unit(int u, int s, float hs, float ts, int doY,
    const float* __restrict__ w1, const float* __restrict__ b1, float* sp) {
  float* As = sp;            // [16][128]
  float* Bs = sp + 2048;     // [16][128]
  const int t = threadIdx.x;
  const int tx = t & 15, ty = t >> 4;
  const int p0 = tx*8, f0 = ty*8;
  float hc[6];
  #pragma unroll
  for (int j = 0; j < 6; j++) hc[j] = hs * c_comb[s][j];
  float bias[8];
  #pragma unroll
  for (int j = 0; j < 8; j++) bias[j] = b1[f0+j] + ts * w1[f0+j];

  const int m0 = u * 128;
  u64 acc[8][4];
  #pragma unroll
  for (int i = 0; i < 8; i++)
    #pragma unroll
    for (int j = 0; j < 4; j++) acc[i][j] = 0ull;

  for (int kk = 0; kk < 64; kk += 16) {
    #pragma unroll
    for (int r = 0; r < 2; r++) {   // A: 128px x 16c combined
      int id = t + 256*r;
      int cq = id & 3, m = id >> 2;
      int fi = (m0 + m)*16 + (kk >> 2) + cq;
      float4 a;
      if (s == 0) {
        if (doY) { a = ((const float4*)g_y5)[fi]; ((float4*)g_y)[fi] = a; }
        else     { a = ((const float4*)g_y)[fi]; }
      } else {
        a = ((const float4*)g_y)[fi];
        #pragma unroll
        for (int j = 0; j < 6; j++) {
          if (j >= s) break;
          float c = hc[j];
          if (c != 0.0f) {
            float4 kv = ((const float4*)g_k[j])[fi];
            a.x = fmaf(c, kv.x, a.x); a.y = fmaf(c, kv.y, a.y);
            a.z = fmaf(c, kv.z, a.z); a.w = fmaf(c, kv.w, a.w);
          }
        }
        if (s == 6) ((float4*)g_y5)[fi] = a;
      }
      As[(cq*4+0)*128+m]=a.x; As[(cq*4+1)*128+m]=a.y;
      As[(cq*4+2)*128+m]=a.z; As[(cq*4+3)*128+m]=a.w;
    }
    #pragma unroll
    for (int r = 0; r < 2; r++) {   // B: 16c x 128f (skip time row)
      int id = t + 256*r;
      int n4 = id & 31, k = id >> 5;
      *(float4*)&Bs[k*128 + n4*4] = *(const float4*)&w1[(1 + kk + k)*FF + n4*4];
    }
    __syncthreads();
    #pragma unroll
    for (int k = 0; k < 16; k++) {
      float4 a0 = *(float4*)&As[k*128 + p0];
      float4 a1 = *(float4*)&As[k*128 + p0 + 4];
      ulonglong2 w01 = *(ulonglong2*)&Bs[k*128 + f0];
      ulonglong2 w23 = *(ulonglong2*)&Bs[k*128 + f0 + 4];
      u64 av[8] = { pk2(a0.x), pk2(a0.y), pk2(a0.z), pk2(a0.w),
                    pk2(a1.x), pk2(a1.y), pk2(a1.z), pk2(a1.w) };
      u64 wv[4] = { w01.x, w01.y, w23.x, w23.y };
      #pragma unroll
      for (int i = 0; i < 8; i++) {
        fma2(acc[i][0], av[i], wv[0]); fma2(acc[i][1], av[i], wv[1]);
        fma2(acc[i][2], av[i], wv[2]); fma2(acc[i][3], av[i], wv[3]);
      }
    }
    __syncthreads();
  }
  #pragma unroll
  for (int i = 0; i < 8; i++) {
    int p = m0 + p0 + i;
    float o[8];
    #pragma unroll
    for (int j = 0; j < 4; j++) {
      float2 v = up2(acc[i][j]);
      float v0 = v.x + bias[2*j], v1 = v.y + bias[2*j+1];
      o[2*j]   = v0 > 0.f ? v0 : 0.f;
      o[2*j+1] = v1 > 0.f ? v1 : 0.f;
    }
    float4* dst = (float4*)&g_h1[(size_t)p*FF + f0];
    dst[0] = make_float4(o[0],o[1],o[2],o[3]);
    dst[1] = make_float4(o[4],o[5],o[6],o[7]);
  }
}

// ----------------------------- conv2 weight prefetch -----------------------
__device__ __forceinline__ void c2w(int j, const float* __restrict__ w2,
                                    float* w_s) {
  const int t = threadIdx.x;
  int ch = j / 3, dy = j - ch*3, c0 = ch*16;
  float* wb = w_s + (j & 1)*W2BUF;
  const float* wsrc = &w2[((size_t)(dy*3))*129*FF + FF];
  #pragma unroll
  for (int r = 0; r < 6; r++) {
    int id = t + 256*r;
    int f4i = id & 31, cw = (id >> 5) & 15, dx = id >> 9;
    cpa16(&wb[(dx*16 + cw)*128 + f4i*4],
          &wsrc[((size_t)dx*129 + c0 + cw)*FF + f4i*4]);
  }
  CP_COMMIT();
}

// ----------------------------- fused conv2+conv3 tile ----------------------
__device__ void conv23_unit(int u, int s, float ts,
    const float* __restrict__ w2, const float* __restrict__ b2,
    const float* __restrict__ w3, const float* __restrict__ b3, float* sp) {
  // ---------------- conv2: 3x3 SAME 129->128 ReLU on (b, 2 rows) ----------
  {
    float* in_s = sp;                  // [16c][4row][68], stride C2STR
    float* w_s  = sp + C2BUF;          // 2 x [3dx][16c][128f]
    const int t = threadIdx.x;
    const int tx = t & 15, ty = t >> 4;
    const int p0 = tx*4, f0 = ty*8;
    const int b = u >> 5, y0 = (u & 31)*2;

    u64 acc[2][4][4];
    #pragma unroll
    for (int r = 0; r < 2; r++)
      #pragma unroll
      for (int i = 0; i < 4; i++)
        #pragma unroll
        for (int j = 0; j < 4; j++) acc[r][i][j] = 0ull;

    const float* base = &g_h1[(size_t)(b*4096)*FF];
    c2w(0, w2, w_s);
    c2w(1, w2, w_s);

    #pragma unroll 1
    for (int ch = 0; ch < 8; ch++) {
      const int c0 = ch*16;
      #pragma unroll
      for (int r = 0; r < 5; r++) {    // halo: 4row x 66px x 16c (1056 f4)
        int id = t + 256*r;
        if (id < 1056) {
          int c4 = id & 3;
          int pos = id >> 2;
          int rr = pos / 66;
          int xp = pos - rr*66;
          int yy = y0 + rr - 1, xx = xp - 1;
          float4 v = make_float4(0.f,0.f,0.f,0.f);
          if (yy >= 0 && yy < 64 && xx >= 0 && xx < 64)
            v = *(const float4*)&base[((size_t)(yy*64 + xx))*FF + c0 + c4*4];
          float* d = &in_s[(c4*4)*C2STR + rr*68 + xp];
          d[0] = v.x; d[C2STR] = v.y; d[2*C2STR] = v.z; d[3*C2STR] = v.w;
        }
      }
      #pragma unroll 1
      for (int dy = 0; dy < 3; dy++) {
        int j = ch*3 + dy;
        if (j < 23) { CP_WAIT1(); } else { CP_WAIT0(); }
        __syncthreads();
        const float* wb = w_s + (j & 1)*W2BUF;
        #pragma unroll 2
        for (int c = 0; c < 16; c++) {
          const float* rA = &in_s[c*C2STR + dy*68 + p0];
          const float* rB = rA + 68;
          float4 v4; float2 v2;
          u64 aA[6], aB[6];
          v4 = *(const float4*)rA; v2 = *(const float2*)(rA+4);
          aA[0]=pk2(v4.x); aA[1]=pk2(v4.y); aA[2]=pk2(v4.z);
          aA[3]=pk2(v4.w); aA[4]=pk2(v2.x); aA[5]=pk2(v2.y);
          v4 = *(const float4*)rB; v2 = *(const float2*)(rB+4);
          aB[0]=pk2(v4.x); aB[1]=pk2(v4.y); aB[2]=pk2(v4.z);
          aB[3]=pk2(v4.w); aB[4]=pk2(v2.x); aB[5]=pk2(v2.y);
          #pragma unroll
          for (int dx = 0; dx < 3; dx++) {
            ulonglong2 w01 = *(const ulonglong2*)&wb[(dx*16+c)*128 + f0];
            ulonglong2 w23 = *(const ulonglong2*)&wb[(dx*16+c)*128 + f0 + 4];
            u64 wv[4] = { w01.x, w01.y, w23.x, w23.y };
            #pragma unroll
            for (int i = 0; i < 4; i++) {
              u64 a0 = aA[i+dx], a1 = aB[i+dx];
              fma2(acc[0][i][0], a0, wv[0]); fma2(acc[0][i][1], a0, wv[1]);
              fma2(acc[0][i][2], a0, wv[2]); fma2(acc[0][i][3], a0, wv[3]);
              fma2(acc[1][i][0], a1, wv[0]); fma2(acc[1][i][1], a1, wv[1]);
              fma2(acc[1][i][2], a1, wv[2]); fma2(acc[1][i][3], a1, wv[3]);
            }
          }
        }
        __syncthreads();
        if (j < 22) c2w(j + 2, w2, w_s);
      }
    }
    #pragma unroll
    for (int row = 0; row < 2; row++) {
      int y = y0 + row;
      int cy = (y == 0) ? 0 : ((y == 63) ? 2 : 1);
      #pragma unroll
      for (int i = 0; i < 4; i++) {
        int x = p0 + i;
        int cx = (x == 0) ? 0 : ((x == 63) ? 2 : 1);
        const float* S = &g_S2[(cy*3+cx)*FF];
        float o[8];
        #pragma unroll
        for (int j = 0; j < 4; j++) {
          float2 v = up2(acc[row][i][j]);
          float v0 = v.x + b2[f0+2*j]   + ts*S[f0+2*j];
          float v1 = v.y + b2[f0+2*j+1] + ts*S[f0+2*j+1];
          o[2*j]   = v0 > 0.f ? v0 : 0.f;
          o[2*j+1] = v1 > 0.f ? v1 : 0.f;
        }
        float4* dst = (float4*)&g_h2[((size_t)((b*64+y)*64 + x))*FF + f0];
        dst[0] = make_float4(o[0],o[1],o[2],o[3]);
        dst[1] = make_float4(o[4],o[5],o[6],o[7]);
      }
    }
  }
  __syncthreads();   // h2 visible intra-block; smem reuse

  // ---------------- conv3: 1x1 129->64 on the same 128 px -----------------
  {
    float* As = sp;            // [16][128]
    float* Bs = sp + 2048;     // [16][64]
    const int t = threadIdx.x;
    const int tx = t & 15, ty = t >> 4;
    const int p0 = tx*8, f0 = ty*4;
    float bias[4];
    #pragma unroll
    for (int j = 0; j < 4; j++) bias[j] = b3[f0+j] + ts*w3[f0+j];
    float* kout = g_k[s];
    const int m0 = u * 128;

    u64 acc[8][2];
    #pragma unroll
    for (int i = 0; i < 8; i++) { acc[i][0] = 0ull; acc[i][1] = 0ull; }

    for (int kk = 0; kk < 128; kk += 16) {
      #pragma unroll
      for (int r = 0; r < 2; r++) {
        int id = t + 256*r;
        int m = id >> 2, cq = id & 3;
        float4 v = *(const float4*)&g_h2[(size_t)(m0+m)*FF + kk + cq*4];
        As[(cq*4+0)*128+m]=v.x; As[(cq*4+1)*128+m]=v.y;
        As[(cq*4+2)*128+m]=v.z; As[(cq*4+3)*128+m]=v.w;
      }
      {
        int n4 = t & 15, k = t >> 4;
        *(float4*)&Bs[k*64 + n4*4] = *(const float4*)&w3[(1 + kk + k)*CC + n4*4];
      }
      __syncthreads();
      #pragma unroll
      for (int k = 0; k < 16; k++) {
        float4 a0 = *(float4*)&As[k*128 + p0];
        float4 a1 = *(float4*)&As[k*128 + p0 + 4];
        ulonglong2 wv = *(ulonglong2*)&Bs[k*64 + f0];
        u64 av[8] = { pk2(a0.x), pk2(a0.y), pk2(a0.z), pk2(a0.w),
                      pk2(a1.x), pk2(a1.y), pk2(a1.z), pk2(a1.w) };
        #pragma unroll
        for (int i = 0; i < 8; i++) {
          fma2(acc[i][0], av[i], wv.x);
          fma2(acc[i][1], av[i], wv.y);
        }
      }
      __syncthreads();
    }
    #pragma unroll
    for (int i = 0; i < 8; i++) {
      int p = m0 + p0 + i;
      float2 v0 = up2(acc[i][0]), v1 = up2(acc[i][1]);
      *(float4*)&kout[(size_t)p*CC + f0] = make_float4(
        v0.x+bias[0], v0.y+bias[1], v1.x+bias[2], v1.y+bias[3]);
    }
  }
}

// ----------------------------- error partial (static, deterministic) -------
__device__ void phase_err(float hs, float* sp) {
  const int t = threadIdx.x;
  __syncthreads();
  float s = 0.0f;
  const float4* k1 = (const float4*)g_k[0];
  const float4* k3 = (const float4*)g_k[2];
  const float4* k4 = (const float4*)g_k[3];
  const float4* k5 = (const float4*)g_k[4];
  const float4* k6 = (const float4*)g_k[5];
  const float4* k7 = (const float4*)g_k[6];
  const float4* yv = (const float4*)g_y;
  const float4* y5 = (const float4*)g_y5;
  for (int i = blockIdx.x*NT + t; i < NY/4; i += GRIDN*NT) {
    float4 a=k1[i], c3=k3[i], c4=k4[i], c5=k5[i], c6=k6[i], c7=k7[i];
    float4 yy=yv[i], z5=y5[i];
    #define ECOMP(M) { \
      float err = hs*(E1f*a.M + E3f*c3.M + E4f*c4.M + E5f*c5.M + E6f*c6.M + E7f*c7.M); \
      float sc = TOLf + TOLf*fmaxf(fabsf(yy.M), fabsf(z5.M)); \
      float r = err/sc; s = fmaf(r, r, s); }
    ECOMP(x) ECOMP(y) ECOMP(z) ECOMP(w)
    #undef ECOMP
  }
  sp[t] = s;
  __syncthreads();
  for (int o = 128; o > 0; o >>= 1) {
    if (t < o) sp[t] += sp[t + o];
    __syncthreads();
  }
  if (t == 0) g_partial[blockIdx.x] = sp[0];
  __syncthreads();
}

// ----------------------------- main persistent kernel ----------------------
__global__ void __launch_bounds__(NT, 2) ode_all(
    const float* __restrict__ x,
    const float* __restrict__ w1, const float* __restrict__ b1,
    const float* __restrict__ w2, const float* __restrict__ b2,
    const float* __restrict__ w3, const float* __restrict__ b3,
    const float* __restrict__ wo, const float* __restrict__ bo,
    float* __restrict__ out) {
  extern __shared__ float sp[];
  const int bid = blockIdx.x, t = threadIdx.x;

  // ---- init
  for (int i = bid*NT + t; i < NY/4; i += GRIDN*NT)
    ((float4*)g_y)[i] = ((const float4*)x)[i];
  if (bid == 0) {
    if (t < FF) {
      int f = t;
      for (int cy = 0; cy < 3; cy++)
        for (int cx = 0; cx < 3; cx++) {
          float s = 0.0f;
          for (int dy = 0; dy < 3; dy++) {
            if (cy == 0 && dy == 0) continue;
            if (cy == 2 && dy == 2) continue;
            for (int dx = 0; dx < 3; dx++) {
              if (cx == 0 && dx == 0) continue;
              if (cx == 2 && dx == 2) continue;
              s += w2[((size_t)(dy*3+dx)*129 + 0)*FF + f];
            }
          }
          g_S2[(cy*3+cx)*FF + f] = s;
        }
    }
    if (t == 0) {
      g_t = 0.0f; g_h = 0.1f; g_hs = 0.1f; g_done = 0; g_accept = 0;
      g_ticket = 0u;
    }
  }
  gbar();

  unsigned tb = 0;   // ticket base, advanced identically by all blocks
  for (int iter = 0; iter < NITER; iter++) {
    if (*(volatile int*)&g_done) break;
    float hs = *(volatile float*)&g_hs;
    float tc = *(volatile float*)&g_t;
    int doY  = *(volatile int*)&g_accept;

    for (int s = 0; s < 7; s++) {
      float ts = tc + c_cs[s]*hs;
      int u;
      while ((u = steal(tb)) >= 0)
        conv1_unit(u, s, hs, ts, doY, w1, b1, sp);
      tb += NU + GRIDN;
      gbar();                             // h1 complete
      while ((u = steal(tb)) >= 0)
        conv23_unit(u, s, ts, w2, b2, w3, b3, sp);
      tb += NU + GRIDN;
      gbar();                             // k[s] complete
    }
    phase_err(hs, sp);
    gbar();

    if (bid == 0) {
      float ssum = 0.0f;
      for (int i = t; i < GRIDN; i += NT) ssum += g_partial[i];
      sp[t] = ssum;
      __syncthreads();
      for (int o = 128; o > 0; o >>= 1) {
        if (t < o) sp[t] += sp[t + o];
        __syncthreads();
      }
      if (t == 0) {
        float en = sqrtf(sp[0] / (float)NY);
        float hcur = g_hs;
        int acc = (en <= 1.0f) ? 1 : 0;
        g_accept = acc;
        float tn = acc ? (g_t + hcur) : g_t;
        g_t = tn;
        float ens = fmaxf(en, 1e-8f);
        float fac = fminf(fmaxf(0.9f * powf(ens, -0.2f), 0.2f), 10.0f);
        float hn = fmaxf(hcur * fac, 1e-4f);
        g_h = hn;
        g_done = (tn >= 1.0f) ? 1 : 0;
        g_hs = fminf(hn, 1.0f - tn);
      }
    }
    gbar();
  }
  // final state selector: if last control accepted, solution is y5.
  const float* yfin = (*(volatile int*)&g_accept) ? g_y5 : g_y;

  // ---- output head: 1x1 conv 64 -> 10 (static px ownership)
  if (bid < 256) {
    float* ws = sp;
    float* bs = sp + 640;
    __syncthreads();
    for (int i = t; i < CC*OUTC; i += NT) ws[i] = wo[i];
    if (t < OUTC) bs[t] = bo[t];
    __syncthreads();
    if (t < 128) {
      int p = bid*128 + t;
      float accs[OUTC];
      #pragma unroll
      for (int j = 0; j < OUTC; j++) accs[j] = bs[j];
      #pragma unroll
      for (int c4 = 0; c4 < 16; c4++) {
        float4 v = *(const float4*)&yfin[(size_t)p*CC + c4*4];
        float vv[4] = {v.x, v.y, v.z, v.w};
        #pragma unroll
        for (int q = 0; q < 4; q++)
          #pragma unroll
          for (int j = 0; j < OUTC; j++)
            accs[j] = fmaf(vv[q], ws[(c4*4+q)*OUTC + j], accs[j]);
      }
      #pragma unroll
      for (int j = 0; j < OUTC; j++) out[(size_t)p*OUTC + j] = accs[j];
    }
  }
}

// ----------------------------- launcher -------------------------------------
extern "C" void kernel_launch(void* const* d_in, const int* in_sizes, int n_in,
                              void* d_out, int out_size) {
  const float* x  = (const float*)d_in[0];
  const float* w1 = (const float*)d_in[1];
  const float* b1 = (const float*)d_in[2];
  const float* w2 = (const float*)d_in[3];
  const float* b2 = (const float*)d_in[4];
  const float* w3 = (const float*)d_in[5];
  const float* b3 = (const float*)d_in[6];
  const float* wo = (const float*)d_in[7];
  const float* bo = (const float*)d_in[8];
  float* out = (float*)d_out;

  cudaFuncSetAttribute(ode_all, cudaFuncAttributeMaxDynamicSharedMemorySize,
                       SPOOL_BYTES);
  ode_all<<<GRIDN, NT, SPOOL_BYTES>>>(x, w1, b1, w2, b2, w3, b3, wo, bo, out);
}

// round 13
// speedup vs baseline: 1.1350x; 1.1350x over previous
#include <cuda_runtime.h>
#include <math.h>

// Conv2dODENet dopri5 — persistent kernel. R13 = R10 skeleton +
//   (1) FSAL: skip stage-0 eval after iter 0 (k1 <- k7 on accept)
//   (2) conv2 triple-buffered weight pipeline (fewer syncs, issue-before-compute)
#define CC 64
#define FF 128
#define OUTC 10
#define NPIX 32768
#define NY (NPIX*CC)
#define NH (NPIX*FF)
#define GRIDN 296
#define NWORK 256
#define NT 256
#define NITER 32
#define C2STR 276                 // conv2 in_s channel stride (floats)
#define C2BUF (16*C2STR)          // 4416
#define W2BUF 6144
#define SPOOL (C2BUF + 3*W2BUF)   // 22848 floats = 91392 B
#define SPOOL_BYTES (SPOOL*4)

typedef unsigned long long u64;

__device__ __forceinline__ u64 pk2(float x) {
  u64 r; asm("mov.b64 %0, {%1, %1};" : "=l"(r) : "r"(__float_as_uint(x))); return r;
}
__device__ __forceinline__ void fma2(u64 &d, u64 a, u64 b) {
  asm("fma.rn.f32x2 %0, %1, %2, %3;" : "=l"(d) : "l"(a), "l"(b), "l"(d));
}
__device__ __forceinline__ float2 up2(u64 v) {
  unsigned lo, hi;
  asm("mov.b64 {%0, %1}, %2;" : "=r"(lo), "=r"(hi) : "l"(v));
  return make_float2(__uint_as_float(lo), __uint_as_float(hi));
}
__device__ __forceinline__ void cpa16(float* dst, const float* src) {
  unsigned d = (unsigned)__cvta_generic_to_shared(dst);
  asm volatile("cp.async.cg.shared.global [%0], [%1], 16;" :: "r"(d), "l"(src));
}
#define CP_COMMIT() asm volatile("cp.async.commit_group;" ::: "memory")
#define CP_WAIT1()  asm volatile("cp.async.wait_group 1;" ::: "memory")
#define CP_WAIT0()  asm volatile("cp.async.wait_group 0;" ::: "memory")

// ----------------------------- device state --------------------------------
__device__ float g_y[NY];
__device__ float g_y5[NY];
__device__ float g_k[7][NY];
__device__ float g_h1[2][NH];     // parity double-buffer (cross-block halo)
__device__ float g_h2[NH];
__device__ float g_S2[9*FF];
__device__ float g_partial[GRIDN];
__device__ float g_t, g_h, g_hs;
__device__ int   g_done, g_accept;
__device__ unsigned g_bar_in, g_bar_gen;

__constant__ float c_comb[7][6] = {
  { 0,0,0,0,0,0 },
  { (float)(1.0/5.0), 0,0,0,0,0 },
  { (float)(3.0/40.0), (float)(9.0/40.0), 0,0,0,0 },
  { (float)(44.0/45.0), (float)(-56.0/15.0), (float)(32.0/9.0), 0,0,0 },
  { (float)(19372.0/6561.0), (float)(-25360.0/2187.0), (float)(64448.0/6561.0),
    (float)(-212.0/729.0), 0,0 },
  { (float)(9017.0/3168.0), (float)(-355.0/33.0), (float)(46732.0/5247.0),
    (float)(49.0/176.0), (float)(-5103.0/18656.0), 0 },
  { (float)(35.0/384.0), 0.0f, (float)(500.0/1113.0), (float)(125.0/192.0),
    (float)(-2187.0/6784.0), (float)(11.0/84.0) },
};
__constant__ float c_cs[7] = { 0.0f, (float)(1.0/5.0), (float)(3.0/10.0),
  (float)(4.0/5.0), (float)(8.0/9.0), 1.0f, 1.0f };

#define E1f ((float)(71.0/57600.0))
#define E3f ((float)(-71.0/16695.0))
#define E4f ((float)(71.0/1920.0))
#define E5f ((float)(-17253.0/339200.0))
#define E6f ((float)(22.0/525.0))
#define E7f ((float)(-1.0/40.0))
#define TOLf 1e-3f

// ----------------------------- grid barrier --------------------------------
__device__ __forceinline__ void gbar() {
  __syncthreads();
  if (threadIdx.x == 0) {
    __threadfence();
    unsigned gen = *(volatile unsigned*)&g_bar_gen;
    if (atomicAdd(&g_bar_in, 1u) == GRIDN - 1u) {
      g_bar_in = 0u;
      __threadfence();
      *(volatile unsigned*)&g_bar_gen = gen + 1u;
    } else {
      while (*(volatile unsigned*)&g_bar_gen == gen) { __nanosleep(64); }
    }
    __threadfence();
  }
  __syncthreads();
}

// ----------------------------- conv1: 1x1, 65->128, ReLU -------------------
__device__ void phase_conv1(int s, float hs, float ts,
    const float* __restrict__ w1, const float* __restrict__ b1, float* sp,
    float* __restrict__ h1out) {
  float* As = sp;            // [16][128]
  float* Bs = sp + 2048;     // [16][128]
  const int t = threadIdx.x;
  const int tx = t & 15, ty = t >> 4;
  const int p0 = tx*8, f0 = ty*8;
  float hc[6];
  #pragma unroll
  for (int j = 0; j < 6; j++) hc[j] = hs * c_comb[s][j];
  float bias[8];
  #pragma unroll
  for (int j = 0; j < 8; j++) bias[j] = b1[f0+j] + ts * w1[f0+j];

  __syncthreads();   // entry: prior-phase writes + smem reuse

  const int m0 = blockIdx.x * 128;
  u64 acc[8][4];
  #pragma unroll
  for (int i = 0; i < 8; i++)
    #pragma unroll
    for (int j = 0; j < 4; j++) acc[i][j] = 0ull;

  for (int kk = 0; kk < 64; kk += 16) {
    #pragma unroll
    for (int r = 0; r < 2; r++) {   // A: 128px x 16c combined
      int id = t + 256*r;
      int cq = id & 3, m = id >> 2;
      int fi = (m0 + m)*16 + (kk >> 2) + cq;
      float4 a = ((const float4*)g_y)[fi];
      if (s > 0) {
        #pragma unroll
        for (int j = 0; j < 6; j++) {
          if (j >= s) break;
          float c = hc[j];
          if (c != 0.0f) {
            float4 kv = ((const float4*)g_k[j])[fi];
            a.x = fmaf(c, kv.x, a.x); a.y = fmaf(c, kv.y, a.y);
            a.z = fmaf(c, kv.z, a.z); a.w = fmaf(c, kv.w, a.w);
          }
        }
        if (s == 6) ((float4*)g_y5)[fi] = a;
      }
      As[(cq*4+0)*128+m]=a.x; As[(cq*4+1)*128+m]=a.y;
      As[(cq*4+2)*128+m]=a.z; As[(cq*4+3)*128+m]=a.w;
    }
    #pragma unroll
    for (int r = 0; r < 2; r++) {   // B: 16c x 128f (skip time row)
      int id = t + 256*r;
      int n4 = id & 31, k = id >> 5;
      *(float4*)&Bs[k*128 + n4*4] = *(const float4*)&w1[(1 + kk + k)*FF + n4*4];
    }
    __syncthreads();
    #pragma unroll
    for (int k = 0; k < 16; k++) {
      float4 a0 = *(float4*)&As[k*128 + p0];
      float4 a1 = *(float4*)&As[k*128 + p0 + 4];
      ulonglong2 w01 = *(ulonglong2*)&Bs[k*128 + f0];
      ulonglong2 w23 = *(ulonglong2*)&Bs[k*128 + f0 + 4];
      u64 av[8] = { pk2(a0.x), pk2(a0.y), pk2(a0.z), pk2(a0.w),
                    pk2(a1.x), pk2(a1.y), pk2(a1.z), pk2(a1.w) };
      u64 wv[4] = { w01.x, w01.y, w23.x, w23.y };
      #pragma unroll
      for (int i = 0; i < 8; i++) {
        fma2(acc[i][0], av[i], wv[0]); fma2(acc[i][1], av[i], wv[1]);
        fma2(acc[i][2], av[i], wv[2]); fma2(acc[i][3], av[i], wv[3]);
      }
    }
    __syncthreads();
  }
  #pragma unroll
  for (int i = 0; i < 8; i++) {
    int p = m0 + p0 + i;
    float o[8];
    #pragma unroll
    for (int j = 0; j < 4; j++) {
      float2 v = up2(acc[i][j]);
      float v0 = v.x + bias[2*j], v1 = v.y + bias[2*j+1];
      o[2*j]   = v0 > 0.f ? v0 : 0.f;
      o[2*j+1] = v1 > 0.f ? v1 : 0.f;
    }
    float4* dst = (float4*)&h1out[(size_t)p*FF + f0];
    dst[0] = make_float4(o[0],o[1],o[2],o[3]);
    dst[1] = make_float4(o[4],o[5],o[6],o[7]);
  }
}

// ----------------------------- conv2 weight prefetch (group j -> buf j%3) --
__device__ __forceinline__ void conv2_issue_w(int j,
    const float* __restrict__ w2, float* w_s) {
  const int t = threadIdx.x;
  int ch = j / 3, dy = j - ch*3, c0 = ch*16;
  float* wb = w_s + (j % 3)*W2BUF;
  const float* wsrc = &w2[((size_t)(dy*3))*129*FF + FF];   // (dy,0,cin=1,f=0)
  #pragma unroll
  for (int r = 0; r < 6; r++) {
    int id = t + 256*r;
    int f4i = id & 31, cw = (id >> 5) & 15, dx = id >> 9;
    cpa16(&wb[(dx*16 + cw)*128 + f4i*4],
          &wsrc[((size_t)dx*129 + c0 + cw)*FF + f4i*4]);
  }
  CP_COMMIT();
}

// ----------------------------- conv2: 3x3 SAME, 129->128, ReLU -------------
__device__ void phase_conv2(float ts,
    const float* __restrict__ w2, const float* __restrict__ b2, float* sp,
    const float* __restrict__ h1buf) {
  float* in_s = sp;                  // [16c][4row][68], stride C2STR
  float* w_s  = sp + C2BUF;          // 3 x [3dx][16c][128f]
  const int t = threadIdx.x;
  const int tx = t & 15, ty = t >> 4;
  const int p0 = tx*4, f0 = ty*8;
  const int tile = blockIdx.x;
  const int b = tile >> 5, y0 = (tile & 31)*2;

  u64 acc[2][4][4];
  #pragma unroll
  for (int r = 0; r < 2; r++)
    #pragma unroll
    for (int i = 0; i < 4; i++)
      #pragma unroll
      for (int j = 0; j < 4; j++) acc[r][i][j] = 0ull;

  const float* base = &h1buf[(size_t)(b*4096)*FF];

  conv2_issue_w(0, w2, w_s);
  conv2_issue_w(1, w2, w_s);

  #pragma unroll 1
  for (int ch = 0; ch < 8; ch++) {
    const int c0 = ch*16;
    __syncthreads();                 // all reads of in_s (prev chunk) done
    // ---- halo: 4 rows x 66 px x 16 c (1056 f4, sync LDG -> 4x STS)
    #pragma unroll
    for (int r = 0; r < 5; r++) {
      int id = t + 256*r;
      if (id < 1056) {
        int c4 = id & 3;
        int pos = id >> 2;           // 0..263
        int rr = pos / 66;
        int xp = pos - rr*66;
        int yy = y0 + rr - 1, xx = xp - 1;
        float4 v = make_float4(0.f,0.f,0.f,0.f);
        if (yy >= 0 && yy < 64 && xx >= 0 && xx < 64)
          v = *(const float4*)&base[((size_t)(yy*64 + xx))*FF + c0 + c4*4];
        float* d = &in_s[(c4*4)*C2STR + rr*68 + xp];
        d[0] = v.x; d[C2STR] = v.y; d[2*C2STR] = v.z; d[3*C2STR] = v.w;
      }
    }
    #pragma unroll 1
    for (int dy = 0; dy < 3; dy++) {
      int j = ch*3 + dy;
      if (j < 23) { CP_WAIT1(); } else { CP_WAIT0(); }
      __syncthreads();               // halo (dy0) + weights(j) visible
      if (j < 22) conv2_issue_w(j + 2, w2, w_s);   // buf (j+2)%3: drained
      const float* wb = w_s + (j % 3)*W2BUF;
      #pragma unroll 2
      for (int c = 0; c < 16; c++) {
        const float* rA = &in_s[c*C2STR + dy*68 + p0];
        const float* rB = rA + 68;
        float4 v4; float2 v2;
        u64 aA[6], aB[6];
        v4 = *(const float4*)rA; v2 = *(const float2*)(rA+4);
        aA[0]=pk2(v4.x); aA[1]=pk2(v4.y); aA[2]=pk2(v4.z);
        aA[3]=pk2(v4.w); aA[4]=pk2(v2.x); aA[5]=pk2(v2.y);
        v4 = *(const float4*)rB; v2 = *(const float2*)(rB+4);
        aB[0]=pk2(v4.x); aB[1]=pk2(v4.y); aB[2]=pk2(v4.z);
        aB[3]=pk2(v4.w); aB[4]=pk2(v2.x); aB[5]=pk2(v2.y);
        #pragma unroll
        for (int dx = 0; dx < 3; dx++) {
          ulonglong2 w01 = *(const ulonglong2*)&wb[(dx*16+c)*128 + f0];
          ulonglong2 w23 = *(const ulonglong2*)&wb[(dx*16+c)*128 + f0 + 4];
          u64 wv[4] = { w01.x, w01.y, w23.x, w23.y };
          #pragma unroll
          for (int i = 0; i < 4; i++) {
            u64 a0 = aA[i+dx], a1 = aB[i+dx];
            fma2(acc[0][i][0], a0, wv[0]); fma2(acc[0][i][1], a0, wv[1]);
            fma2(acc[0][i][2], a0, wv[2]); fma2(acc[0][i][3], a0, wv[3]);
            fma2(acc[1][i][0], a1, wv[0]); fma2(acc[1][i][1], a1, wv[1]);
            fma2(acc[1][i][2], a1, wv[2]); fma2(acc[1][i][3], a1, wv[3]);
          }
        }
      }
      // no post-compute sync: triple-buffered weights; halo sync at chunk top
    }
  }

  #pragma unroll
  for (int row = 0; row < 2; row++) {
    int y = y0 + row;
    int cy = (y == 0) ? 0 : ((y == 63) ? 2 : 1);
    #pragma unroll
    for (int i = 0; i < 4; i++) {
      int x = p0 + i;
      int cx = (x == 0) ? 0 : ((x == 63) ? 2 : 1);
      const float* S = &g_S2[(cy*3+cx)*FF];
      float o[8];
      #pragma unroll
      for (int j = 0; j < 4; j++) {
        float2 v = up2(acc[row][i][j]);
        float v0 = v.x + b2[f0+2*j]   + ts*S[f0+2*j];
        float v1 = v.y + b2[f0+2*j+1] + ts*S[f0+2*j+1];
        o[2*j]   = v0 > 0.f ? v0 : 0.f;
        o[2*j+1] = v1 > 0.f ? v1 : 0.f;
      }
      float4* dst = (float4*)&g_h2[((size_t)((b*64+y)*64 + x))*FF + f0];
      dst[0] = make_float4(o[0],o[1],o[2],o[3]);
      dst[1] = make_float4(o[4],o[5],o[6],o[7]);
    }
  }
}

// ----------------------------- conv3: 1x1, 129->64 -------------------------
__device__ void phase_conv3(int s, float ts,
    const float* __restrict__ w3, const float* __restrict__ b3, float* sp) {
  float* As = sp;            // [16][128]
  float* Bs = sp + 2048;     // [16][64]
  const int t = threadIdx.x;
  const int tx = t & 15, ty = t >> 4;
  const int p0 = tx*8, f0 = ty*4;
  float bias[4];
  #pragma unroll
  for (int j = 0; j < 4; j++) bias[j] = b3[f0+j] + ts*w3[f0+j];
  float* kout = g_k[s];
  const int m0 = blockIdx.x * 128;

  u64 acc[8][2];
  #pragma unroll
  for (int i = 0; i < 8; i++) { acc[i][0] = 0ull; acc[i][1] = 0ull; }

  for (int kk = 0; kk < 128; kk += 16) {
    #pragma unroll
    for (int r = 0; r < 2; r++) {
      int id = t + 256*r;
      int m = id >> 2, cq = id & 3;
      float4 v = *(const float4*)&g_h2[(size_t)(m0+m)*FF + kk + cq*4];
      As[(cq*4+0)*128+m]=v.x; As[(cq*4+1)*128+m]=v.y;
      As[(cq*4+2)*128+m]=v.z; As[(cq*4+3)*128+m]=v.w;
    }
    {
      int n4 = t & 15, k = t >> 4;
      *(float4*)&Bs[k*64 + n4*4] = *(const float4*)&w3[(1 + kk + k)*CC + n4*4];
    }
    __syncthreads();
    #pragma unroll
    for (int k = 0; k < 16; k++) {
      float4 a0 = *(float4*)&As[k*128 + p0];
      float4 a1 = *(float4*)&As[k*128 + p0 + 4];
      ulonglong2 wv = *(ulonglong2*)&Bs[k*64 + f0];
      u64 av[8] = { pk2(a0.x), pk2(a0.y), pk2(a0.z), pk2(a0.w),
                    pk2(a1.x), pk2(a1.y), pk2(a1.z), pk2(a1.w) };
      #pragma unroll
      for (int i = 0; i < 8; i++) {
        fma2(acc[i][0], av[i], wv.x);
        fma2(acc[i][1], av[i], wv.y);
      }
    }
    __syncthreads();
  }
  #pragma unroll
  for (int i = 0; i < 8; i++) {
    int p = m0 + p0 + i;
    float2 v0 = up2(acc[i][0]), v1 = up2(acc[i][1]);
    *(float4*)&kout[(size_t)p*CC + f0] = make_float4(
      v0.x+bias[0], v0.y+bias[1], v1.x+bias[2], v1.y+bias[3]);
  }
}

// ----------------------------- error partial (own px) ----------------------
__device__ void phase_err(float hs, float* sp) {
  const int t = threadIdx.x;
  __syncthreads();
  float s = 0.0f;
  const int base4 = blockIdx.x * 2048;
  const float4* k1 = (const float4*)g_k[0];
  const float4* k3 = (const float4*)g_k[2];
  const float4* k4 = (const float4*)g_k[3];
  const float4* k5 = (const float4*)g_k[4];
  const float4* k6 = (const float4*)g_k[5];
  const float4* k7 = (const float4*)g_k[6];
  const float4* yv = (const float4*)g_y;
  const float4* y5 = (const float4*)g_y5;
  for (int q = t; q < 2048; q += NT) {
    int i = base4 + q;
    float4 a=k1[i], c3=k3[i], c4=k4[i], c5=k5[i], c6=k6[i], c7=k7[i];
    float4 yy=yv[i], z5=y5[i];
    #define ECOMP(M) { \
      float err = hs*(E1f*a.M + E3f*c3.M + E4f*c4.M + E5f*c5.M + E6f*c6.M + E7f*c7.M); \
      float sc = TOLf + TOLf*fmaxf(fabsf(yy.M), fabsf(z5.M)); \
      float r = err/sc; s = fmaf(r, r, s); }
    ECOMP(x) ECOMP(y) ECOMP(z) ECOMP(w)
    #undef ECOMP
  }
  sp[t] = s;
  __syncthreads();
  for (int o = 128; o > 0; o >>= 1) {
    if (t < o) sp[t] += sp[t + o];
    __syncthreads();
  }
  if (t == 0) g_partial[blockIdx.x] = sp[0];
  __syncthreads();
}

// ----------------------------- main persistent kernel ----------------------
__global__ void __launch_bounds__(NT, 2) ode_all(
    const float* __restrict__ x,
    const float* __restrict__ w1, const float* __restrict__ b1,
    const float* __restrict__ w2, const float* __restrict__ b2,
    const float* __restrict__ w3, const float* __restrict__ b3,
    const float* __restrict__ wo, const float* __restrict__ bo,
    float* __restrict__ out) {
  extern __shared__ float sp[];
  const int bid = blockIdx.x, t = threadIdx.x;
  const bool work = (bid < NWORK);

  // ---- init
  for (int i = bid*NT + t; i < NY/4; i += GRIDN*NT)
    ((float4*)g_y)[i] = ((const float4*)x)[i];
  if (bid == 0) {
    if (t < FF) {
      int f = t;
      for (int cy = 0; cy < 3; cy++)
        for (int cx = 0; cx < 3; cx++) {
          float s = 0.0f;
          for (int dy = 0; dy < 3; dy++) {
            if (cy == 0 && dy == 0) continue;
            if (cy == 2 && dy == 2) continue;
            for (int dx = 0; dx < 3; dx++) {
              if (cx == 0 && dx == 0) continue;
              if (cx == 2 && dx == 2) continue;
              s += w2[((size_t)(dy*3+dx)*129 + 0)*FF + f];
            }
          }
          g_S2[(cy*3+cx)*FF + f] = s;
        }
    }
    if (t == 0) { g_t = 0.0f; g_h = 0.1f; g_hs = 0.1f; g_done = 0; g_accept = 0; }
  }
  gbar();

  for (int iter = 0; iter < NITER; iter++) {
    if (*(volatile int*)&g_done) break;
    float hs = *(volatile float*)&g_hs;
    float tc = *(volatile float*)&g_t;

    // FSAL: after the first iteration, k1 is already correct
    // (copied from k7 on accept; untouched on reject).
    const int s0 = (iter == 0) ? 0 : 1;
    for (int s = s0; s < 7; s++) {
      float ts = tc + c_cs[s]*hs;
      float* h1b = g_h1[s & 1];
      if (work) phase_conv1(s, hs, ts, w1, b1, sp, h1b);
      gbar();                                   // h1 halo ready for conv2
      if (work) {
        phase_conv2(ts, w2, b2, sp, h1b);
        __syncthreads();                        // h2 + smem reuse
        phase_conv3(s, ts, w3, b3, sp);
      }
    }
    if (work) phase_err(hs, sp);
    gbar();                                     // partials -> control

    if (bid == 0) {
      float ssum = 0.0f;
      for (int i = t; i < NWORK; i += NT) ssum += g_partial[i];
      sp[t] = ssum;
      __syncthreads();
      for (int o = 128; o > 0; o >>= 1) {
        if (t < o) sp[t] += sp[t + o];
        __syncthreads();
      }
      if (t == 0) {
        float en = sqrtf(sp[0] / (float)NY);
        float hcur = g_hs;
        int acc = (en <= 1.0f) ? 1 : 0;
        g_accept = acc;
        float tn = acc ? (g_t + hcur) : g_t;
        g_t = tn;
        float ens = fmaxf(en, 1e-8f);
        float fac = fminf(fmaxf(0.9f * powf(ens, -0.2f), 0.2f), 10.0f);
        float hn = fmaxf(hcur * fac, 1e-4f);
        g_h = hn;
        g_done = (tn >= 1.0f) ? 1 : 0;
        g_hs = fminf(hn, 1.0f - tn);
      }
    }
    gbar();                                     // control -> everyone

    if (work && *(volatile int*)&g_accept) {    // accept: y <- y5, k1 <- k7
      int base4 = bid * 2048;
      for (int q = t; q < 2048; q += NT) {
        ((float4*)g_y)[base4 + q]    = ((const float4*)g_y5)[base4 + q];
        ((float4*)g_k[0])[base4 + q] = ((const float4*)g_k[6])[base4 + q];
      }
    }
  }
  gbar();

  // ---- output head: 1x1 conv 64 -> 10 (own px)
  if (work) {
    float* ws = sp;
    float* bs = sp + 640;
    __syncthreads();
    for (int i = t; i < CC*OUTC; i += NT) ws[i] = wo[i];
    if (t < OUTC) bs[t] = bo[t];
    __syncthreads();
    if (t < 128) {
      int p = bid*128 + t;
      float accs[OUTC];
      #pragma unroll
      for (int j = 0; j < OUTC; j++) accs[j] = bs[j];
      #pragma unroll
      for (int c4 = 0; c4 < 16; c4++) {
        float4 v = *(const float4*)&g_y[(size_t)p*CC + c4*4];
        float vv[4] = {v.x, v.y, v.z, v.w};
        #pragma unroll
        for (int q = 0; q < 4; q++)
          #pragma unroll
          for (int j = 0; j < OUTC; j++)
            accs[j] = fmaf(vv[q], ws[(c4*4+q)*OUTC + j], accs[j]);
      }
      #pragma unroll
      for (int j = 0; j < OUTC; j++) out[(size_t)p*OUTC + j] = accs[j];
    }
  }
}

// ----------------------------- launcher -------------------------------------
extern "C" void kernel_launch(void* const* d_in, const int* in_sizes, int n_in,
                              void* d_out, int out_size) {
  const float* x  = (const float*)d_in[0];
  const float* w1 = (const float*)d_in[1];
  const float* b1 = (const float*)d_in[2];
  const float* w2 = (const float*)d_in[3];
  const float* b2 = (const float*)d_in[4];
  const float* w3 = (const float*)d_in[5];
  const float* b3 = (const float*)d_in[6];
  const float* wo = (const float*)d_in[7];
  const float* bo = (const float*)d_in[8];
  float* out = (float*)d_out;

  cudaFuncSetAttribute(ode_all, cudaFuncAttributeMaxDynamicSharedMemorySize,
                       SPOOL_BYTES);
  ode_all<<<GRIDN, NT, SPOOL_BYTES>>>(x, w1, b1, w2, b2, w3, b3, wo, bo, out);
}

// round 14
// speedup vs baseline: 1.1358x; 1.0007x over previous
#include <cuda_runtime.h>
#include <math.h>

// Conv2dODENet dopri5 — persistent kernel. R14 = R13 +
//   neighbor-flag sync replaces per-stage global barrier (2 gbar/iter remain)
#define CC 64
#define FF 128
#define OUTC 10
#define NPIX 32768
#define NY (NPIX*CC)
#define NH (NPIX*FF)
#define GRIDN 296
#define NWORK 256
#define NT 256
#define NITER 32
#define C2STR 276                 // conv2 in_s channel stride (floats)
#define C2BUF (16*C2STR)          // 4416
#define W2BUF 6144
#define SPOOL (C2BUF + 3*W2BUF)   // 22848 floats = 91392 B
#define SPOOL_BYTES (SPOOL*4)

typedef unsigned long long u64;

__device__ __forceinline__ u64 pk2(float x) {
  u64 r; asm("mov.b64 %0, {%1, %1};" : "=l"(r) : "r"(__float_as_uint(x))); return r;
}
__device__ __forceinline__ void fma2(u64 &d, u64 a, u64 b) {
  asm("fma.rn.f32x2 %0, %1, %2, %3;" : "=l"(d) : "l"(a), "l"(b), "l"(d));
}
__device__ __forceinline__ float2 up2(u64 v) {
  unsigned lo, hi;
  asm("mov.b64 {%0, %1}, %2;" : "=r"(lo), "=r"(hi) : "l"(v));
  return make_float2(__uint_as_float(lo), __uint_as_float(hi));
}
__device__ __forceinline__ void cpa16(float* dst, const float* src) {
  unsigned d = (unsigned)__cvta_generic_to_shared(dst);
  asm volatile("cp.async.cg.shared.global [%0], [%1], 16;" :: "r"(d), "l"(src));
}
#define CP_COMMIT() asm volatile("cp.async.commit_group;" ::: "memory")
#define CP_WAIT1()  asm volatile("cp.async.wait_group 1;" ::: "memory")
#define CP_WAIT0()  asm volatile("cp.async.wait_group 0;" ::: "memory")

// ----------------------------- device state --------------------------------
__device__ float g_y[NY];
__device__ float g_y5[NY];
__device__ float g_k[7][NY];
__device__ float g_h1[2][NH];     // parity double-buffer (cross-block halo)
__device__ float g_h2[NH];
__device__ float g_S2[9*FF];
__device__ float g_partial[GRIDN];
__device__ float g_t, g_h, g_hs;
__device__ int   g_done, g_accept;
__device__ unsigned g_bar_in, g_bar_gen;
__device__ volatile unsigned g_flag[NWORK];   // per-block conv1 stage counter

__constant__ float c_comb[7][6] = {
  { 0,0,0,0,0,0 },
  { (float)(1.0/5.0), 0,0,0,0,0 },
  { (float)(3.0/40.0), (float)(9.0/40.0), 0,0,0,0 },
  { (float)(44.0/45.0), (float)(-56.0/15.0), (float)(32.0/9.0), 0,0,0 },
  { (float)(19372.0/6561.0), (float)(-25360.0/2187.0), (float)(64448.0/6561.0),
    (float)(-212.0/729.0), 0,0 },
  { (float)(9017.0/3168.0), (float)(-355.0/33.0), (float)(46732.0/5247.0),
    (float)(49.0/176.0), (float)(-5103.0/18656.0), 0 },
  { (float)(35.0/384.0), 0.0f, (float)(500.0/1113.0), (float)(125.0/192.0),
    (float)(-2187.0/6784.0), (float)(11.0/84.0) },
};
__constant__ float c_cs[7] = { 0.0f, (float)(1.0/5.0), (float)(3.0/10.0),
  (float)(4.0/5.0), (float)(8.0/9.0), 1.0f, 1.0f };

#define E1f ((float)(71.0/57600.0))
#define E3f ((float)(-71.0/16695.0))
#define E4f ((float)(71.0/1920.0))
#define E5f ((float)(-17253.0/339200.0))
#define E6f ((float)(22.0/525.0))
#define E7f ((float)(-1.0/40.0))
#define TOLf 1e-3f

// ----------------------------- grid barrier --------------------------------
__device__ __forceinline__ void gbar() {
  __syncthreads();
  if (threadIdx.x == 0) {
    __threadfence();
    unsigned gen = *(volatile unsigned*)&g_bar_gen;
    if (atomicAdd(&g_bar_in, 1u) == GRIDN - 1u) {
      g_bar_in = 0u;
      __threadfence();
      *(volatile unsigned*)&g_bar_gen = gen + 1u;
    } else {
      while (*(volatile unsigned*)&g_bar_gen == gen) { __nanosleep(64); }
    }
    __threadfence();
  }
  __syncthreads();
}

// ----------------------------- conv1: 1x1, 65->128, ReLU -------------------
__device__ void phase_conv1(int s, float hs, float ts,
    const float* __restrict__ w1, const float* __restrict__ b1, float* sp,
    float* __restrict__ h1out) {
  float* As = sp;            // [16][128]
  float* Bs = sp + 2048;     // [16][128]
  const int t = threadIdx.x;
  const int tx = t & 15, ty = t >> 4;
  const int p0 = tx*8, f0 = ty*8;
  float hc[6];
  #pragma unroll
  for (int j = 0; j < 6; j++) hc[j] = hs * c_comb[s][j];
  float bias[8];
  #pragma unroll
  for (int j = 0; j < 8; j++) bias[j] = b1[f0+j] + ts * w1[f0+j];

  __syncthreads();   // entry: prior-phase writes + smem reuse

  const int m0 = blockIdx.x * 128;
  u64 acc[8][4];
  #pragma unroll
  for (int i = 0; i < 8; i++)
    #pragma unroll
    for (int j = 0; j < 4; j++) acc[i][j] = 0ull;

  for (int kk = 0; kk < 64; kk += 16) {
    #pragma unroll
    for (int r = 0; r < 2; r++) {   // A: 128px x 16c combined
      int id = t + 256*r;
      int cq = id & 3, m = id >> 2;
      int fi = (m0 + m)*16 + (kk >> 2) + cq;
      float4 a = ((const float4*)g_y)[fi];
      if (s > 0) {
        #pragma unroll
        for (int j = 0; j < 6; j++) {
          if (j >= s) break;
          float c = hc[j];
          if (c != 0.0f) {
            float4 kv = ((const float4*)g_k[j])[fi];
            a.x = fmaf(c, kv.x, a.x); a.y = fmaf(c, kv.y, a.y);
            a.z = fmaf(c, kv.z, a.z); a.w = fmaf(c, kv.w, a.w);
          }
        }
        if (s == 6) ((float4*)g_y5)[fi] = a;
      }
      As[(cq*4+0)*128+m]=a.x; As[(cq*4+1)*128+m]=a.y;
      As[(cq*4+2)*128+m]=a.z; As[(cq*4+3)*128+m]=a.w;
    }
    #pragma unroll
    for (int r = 0; r < 2; r++) {   // B: 16c x 128f (skip time row)
      int id = t + 256*r;
      int n4 = id & 31, k = id >> 5;
      *(float4*)&Bs[k*128 + n4*4] = *(const float4*)&w1[(1 + kk + k)*FF + n4*4];
    }
    __syncthreads();
    #pragma unroll
    for (int k = 0; k < 16; k++) {
      float4 a0 = *(float4*)&As[k*128 + p0];
      float4 a1 = *(float4*)&As[k*128 + p0 + 4];
      ulonglong2 w01 = *(ulonglong2*)&Bs[k*128 + f0];
      ulonglong2 w23 = *(ulonglong2*)&Bs[k*128 + f0 + 4];
      u64 av[8] = { pk2(a0.x), pk2(a0.y), pk2(a0.z), pk2(a0.w),
                    pk2(a1.x), pk2(a1.y), pk2(a1.z), pk2(a1.w) };
      u64 wv[4] = { w01.x, w01.y, w23.x, w23.y };
      #pragma unroll
      for (int i = 0; i < 8; i++) {
        fma2(acc[i][0], av[i], wv[0]); fma2(acc[i][1], av[i], wv[1]);
        fma2(acc[i][2], av[i], wv[2]); fma2(acc[i][3], av[i], wv[3]);
      }
    }
    __syncthreads();
  }
  #pragma unroll
  for (int i = 0; i < 8; i++) {
    int p = m0 + p0 + i;
    float o[8];
    #pragma unroll
    for (int j = 0; j < 4; j++) {
      float2 v = up2(acc[i][j]);
      float v0 = v.x + bias[2*j], v1 = v.y + bias[2*j+1];
      o[2*j]   = v0 > 0.f ? v0 : 0.f;
      o[2*j+1] = v1 > 0.f ? v1 : 0.f;
    }
    float4* dst = (float4*)&h1out[(size_t)p*FF + f0];
    dst[0] = make_float4(o[0],o[1],o[2],o[3]);
    dst[1] = make_float4(o[4],o[5],o[6],o[7]);
  }
}

// ----------------------------- conv2 weight prefetch (group j -> buf j%3) --
__device__ __forceinline__ void conv2_issue_w(int j,
    const float* __restrict__ w2, float* w_s) {
  const int t = threadIdx.x;
  int ch = j / 3, dy = j - ch*3, c0 = ch*16;
  float* wb = w_s + (j % 3)*W2BUF;
  const float* wsrc = &w2[((size_t)(dy*3))*129*FF + FF];   // (dy,0,cin=1,f=0)
  #pragma unroll
  for (int r = 0; r < 6; r++) {
    int id = t + 256*r;
    int f4i = id & 31, cw = (id >> 5) & 15, dx = id >> 9;
    cpa16(&wb[(dx*16 + cw)*128 + f4i*4],
          &wsrc[((size_t)dx*129 + c0 + cw)*FF + f4i*4]);
  }
  CP_COMMIT();
}

// ----------------------------- conv2: 3x3 SAME, 129->128, ReLU -------------
__device__ void phase_conv2(float ts, unsigned seq,
    const float* __restrict__ w2, const float* __restrict__ b2, float* sp,
    const float* __restrict__ h1buf) {
  float* in_s = sp;                  // [16c][4row][68], stride C2STR
  float* w_s  = sp + C2BUF;          // 3 x [3dx][16c][128f]
  const int t = threadIdx.x;
  const int tx = t & 15, ty = t >> 4;
  const int p0 = tx*4, f0 = ty*8;
  const int tile = blockIdx.x;
  const int b = tile >> 5, y0 = (tile & 31)*2;

  u64 acc[2][4][4];
  #pragma unroll
  for (int r = 0; r < 2; r++)
    #pragma unroll
    for (int i = 0; i < 4; i++)
      #pragma unroll
      for (int j = 0; j < 4; j++) acc[r][i][j] = 0ull;

  const float* base = &h1buf[(size_t)(b*4096)*FF];

  // weights are h1-independent: prefetch before waiting on neighbors
  conv2_issue_w(0, w2, w_s);
  conv2_issue_w(1, w2, w_s);

  // ---- neighbor flag wait: halo rows come from bid-1 / bid+1 (same image)
  if (t == 0) {
    if ((tile & 31) != 0)
      while (g_flag[tile - 1] < seq) { __nanosleep(32); }
    if ((tile & 31) != 31)
      while (g_flag[tile + 1] < seq) { __nanosleep(32); }
    __threadfence();                 // acquire: invalidate L1 before halo reads
  }
  __syncthreads();

  #pragma unroll 1
  for (int ch = 0; ch < 8; ch++) {
    const int c0 = ch*16;
    __syncthreads();                 // all reads of in_s (prev chunk) done
    // ---- halo: 4 rows x 66 px x 16 c (1056 f4, sync LDG -> 4x STS)
    #pragma unroll
    for (int r = 0; r < 5; r++) {
      int id = t + 256*r;
      if (id < 1056) {
        int c4 = id & 3;
        int pos = id >> 2;           // 0..263
        int rr = pos / 66;
        int xp = pos - rr*66;
        int yy = y0 + rr - 1, xx = xp - 1;
        float4 v = make_float4(0.f,0.f,0.f,0.f);
        if (yy >= 0 && yy < 64 && xx >= 0 && xx < 64)
          v = *(const float4*)&base[((size_t)(yy*64 + xx))*FF + c0 + c4*4];
        float* d = &in_s[(c4*4)*C2STR + rr*68 + xp];
        d[0] = v.x; d[C2STR] = v.y; d[2*C2STR] = v.z; d[3*C2STR] = v.w;
      }
    }
    #pragma unroll 1
    for (int dy = 0; dy < 3; dy++) {
      int j = ch*3 + dy;
      if (j < 23) { CP_WAIT1(); } else { CP_WAIT0(); }
      __syncthreads();               // halo (dy0) + weights(j) visible
      if (j < 22) conv2_issue_w(j + 2, w2, w_s);   // buf (j+2)%3: drained
      const float* wb = w_s + (j % 3)*W2BUF;
      #pragma unroll 2
      for (int c = 0; c < 16; c++) {
        const float* rA = &in_s[c*C2STR + dy*68 + p0];
        const float* rB = rA + 68;
        float4 v4; float2 v2;
        u64 aA[6], aB[6];
        v4 = *(const float4*)rA; v2 = *(const float2*)(rA+4);
        aA[0]=pk2(v4.x); aA[1]=pk2(v4.y); aA[2]=pk2(v4.z);
        aA[3]=pk2(v4.w); aA[4]=pk2(v2.x); aA[5]=pk2(v2.y);
        v4 = *(const float4*)rB; v2 = *(const float2*)(rB+4);
        aB[0]=pk2(v4.x); aB[1]=pk2(v4.y); aB[2]=pk2(v4.z);
        aB[3]=pk2(v4.w); aB[4]=pk2(v2.x); aB[5]=pk2(v2.y);
        #pragma unroll
        for (int dx = 0; dx < 3; dx++) {
          ulonglong2 w01 = *(const ulonglong2*)&wb[(dx*16+c)*128 + f0];
          ulonglong2 w23 = *(const ulonglong2*)&wb[(dx*16+c)*128 + f0 + 4];
          u64 wv[4] = { w01.x, w01.y, w23.x, w23.y };
          #pragma unroll
          for (int i = 0; i < 4; i++) {
            u64 a0 = aA[i+dx], a1 = aB[i+dx];
            fma2(acc[0][i][0], a0, wv[0]); fma2(acc[0][i][1], a0, wv[1]);
            fma2(acc[0][i][2], a0, wv[2]); fma2(acc[0][i][3], a0, wv[3]);
            fma2(acc[1][i][0], a1, wv[0]); fma2(acc[1][i][1], a1, wv[1]);
            fma2(acc[1][i][2], a1, wv[2]); fma2(acc[1][i][3], a1, wv[3]);
          }
        }
      }
    }
  }

  #pragma unroll
  for (int row = 0; row < 2; row++) {
    int y = y0 + row;
    int cy = (y == 0) ? 0 : ((y == 63) ? 2 : 1);
    #pragma unroll
    for (int i = 0; i < 4; i++) {
      int x = p0 + i;
      int cx = (x == 0) ? 0 : ((x == 63) ? 2 : 1);
      const float* S = &g_S2[(cy*3+cx)*FF];
      float o[8];
      #pragma unroll
      for (int j = 0; j < 4; j++) {
        float2 v = up2(acc[row][i][j]);
        float v0 = v.x + b2[f0+2*j]   + ts*S[f0+2*j];
        float v1 = v.y + b2[f0+2*j+1] + ts*S[f0+2*j+1];
        o[2*j]   = v0 > 0.f ? v0 : 0.f;
        o[2*j+1] = v1 > 0.f ? v1 : 0.f;
      }
      float4* dst = (float4*)&g_h2[((size_t)((b*64+y)*64 + x))*FF + f0];
      dst[0] = make_float4(o[0],o[1],o[2],o[3]);
      dst[1] = make_float4(o[4],o[5],o[6],o[7]);
    }
  }
}

// ----------------------------- conv3: 1x1, 129->64 -------------------------
__device__ void phase_conv3(int s, float ts,
    const float* __restrict__ w3, const float* __restrict__ b3, float* sp) {
  float* As = sp;            // [16][128]
  float* Bs = sp + 2048;     // [16][64]
  const int t = threadIdx.x;
  const int tx = t & 15, ty = t >> 4;
  const int p0 = tx*8, f0 = ty*4;
  float bias[4];
  #pragma unroll
  for (int j = 0; j < 4; j++) bias[j] = b3[f0+j] + ts*w3[f0+j];
  float* kout = g_k[s];
  const int m0 = blockIdx.x * 128;

  u64 acc[8][2];
  #pragma unroll
  for (int i = 0; i < 8; i++) { acc[i][0] = 0ull; acc[i][1] = 0ull; }

  for (int kk = 0; kk < 128; kk += 16) {
    #pragma unroll
    for (int r = 0; r < 2; r++) {
      int id = t + 256*r;
      int m = id >> 2, cq = id & 3;
      float4 v = *(const float4*)&g_h2[(size_t)(m0+m)*FF + kk + cq*4];
      As[(cq*4+0)*128+m]=v.x; As[(cq*4+1)*128+m]=v.y;
      As[(cq*4+2)*128+m]=v.z; As[(cq*4+3)*128+m]=v.w;
    }
    {
      int n4 = t & 15, k = t >> 4;
      *(float4*)&Bs[k*64 + n4*4] = *(const float4*)&w3[(1 + kk + k)*CC + n4*4];
    }
    __syncthreads();
    #pragma unroll
    for (int k = 0; k < 16; k++) {
      float4 a0 = *(float4*)&As[k*128 + p0];
      float4 a1 = *(float4*)&As[k*128 + p0 + 4];
      ulonglong2 wv = *(ulonglong2*)&Bs[k*64 + f0];
      u64 av[8] = { pk2(a0.x), pk2(a0.y), pk2(a0.z), pk2(a0.w),
                    pk2(a1.x), pk2(a1.y), pk2(a1.z), pk2(a1.w) };
      #pragma unroll
      for (int i = 0; i < 8; i++) {
        fma2(acc[i][0], av[i], wv.x);
        fma2(acc[i][1], av[i], wv.y);
      }
    }
    __syncthreads();
  }
  #pragma unroll
  for (int i = 0; i < 8; i++) {
    int p = m0 + p0 + i;
    float2 v0 = up2(acc[i][0]), v1 = up2(acc[i][1]);
    *(float4*)&kout[(size_t)p*CC + f0] = make_float4(
      v0.x+bias[0], v0.y+bias[1], v1.x+bias[2], v1.y+bias[3]);
  }
}

// ----------------------------- error partial (own px) ----------------------
__device__ void phase_err(float hs, float* sp) {
  const int t = threadIdx.x;
  __syncthreads();
  float s = 0.0f;
  const int base4 = blockIdx.x * 2048;
  const float4* k1 = (const float4*)g_k[0];
  const float4* k3 = (const float4*)g_k[2];
  const float4* k4 = (const float4*)g_k[3];
  const float4* k5 = (const float4*)g_k[4];
  const float4* k6 = (const float4*)g_k[5];
  const float4* k7 = (const float4*)g_k[6];
  const float4* yv = (const float4*)g_y;
  const float4* y5 = (const float4*)g_y5;
  for (int q = t; q < 2048; q += NT) {
    int i = base4 + q;
    float4 a=k1[i], c3=k3[i], c4=k4[i], c5=k5[i], c6=k6[i], c7=k7[i];
    float4 yy=yv[i], z5=y5[i];
    #define ECOMP(M) { \
      float err = hs*(E1f*a.M + E3f*c3.M + E4f*c4.M + E5f*c5.M + E6f*c6.M + E7f*c7.M); \
      float sc = TOLf + TOLf*fmaxf(fabsf(yy.M), fabsf(z5.M)); \
      float r = err/sc; s = fmaf(r, r, s); }
    ECOMP(x) ECOMP(y) ECOMP(z) ECOMP(w)
    #undef ECOMP
  }
  sp[t] = s;
  __syncthreads();
  for (int o = 128; o > 0; o >>= 1) {
    if (t < o) sp[t] += sp[t + o];
    __syncthreads();
  }
  if (t == 0) g_partial[blockIdx.x] = sp[0];
  __syncthreads();
}

// ----------------------------- main persistent kernel ----------------------
__global__ void __launch_bounds__(NT, 2) ode_all(
    const float* __restrict__ x,
    const float* __restrict__ w1, const float* __restrict__ b1,
    const float* __restrict__ w2, const float* __restrict__ b2,
    const float* __restrict__ w3, const float* __restrict__ b3,
    const float* __restrict__ wo, const float* __restrict__ bo,
    float* __restrict__ out) {
  extern __shared__ float sp[];
  const int bid = blockIdx.x, t = threadIdx.x;
  const bool work = (bid < NWORK);

  // ---- init
  for (int i = bid*NT + t; i < NY/4; i += GRIDN*NT)
    ((float4*)g_y)[i] = ((const float4*)x)[i];
  if (work && t == 0) g_flag[bid] = 0u;       // reset flags each replay
  if (bid == 0) {
    if (t < FF) {
      int f = t;
      for (int cy = 0; cy < 3; cy++)
        for (int cx = 0; cx < 3; cx++) {
          float s = 0.0f;
          for (int dy = 0; dy < 3; dy++) {
            if (cy == 0 && dy == 0) continue;
            if (cy == 2 && dy == 2) continue;
            for (int dx = 0; dx < 3; dx++) {
              if (cx == 0 && dx == 0) continue;
              if (cx == 2 && dx == 2) continue;
              s += w2[((size_t)(dy*3+dx)*129 + 0)*FF + f];
            }
          }
          g_S2[(cy*3+cx)*FF + f] = s;
        }
    }
    if (t == 0) { g_t = 0.0f; g_h = 0.1f; g_hs = 0.1f; g_done = 0; g_accept = 0; }
  }
  gbar();

  unsigned seq = 0;
  for (int iter = 0; iter < NITER; iter++) {
    if (*(volatile int*)&g_done) break;
    float hs = *(volatile float*)&g_hs;
    float tc = *(volatile float*)&g_t;

    const int s0 = (iter == 0) ? 0 : 1;       // FSAL
    for (int s = s0; s < 7; s++) {
      float ts = tc + c_cs[s]*hs;
      float* h1b = g_h1[s & 1];
      seq++;
      if (work) {
        phase_conv1(s, hs, ts, w1, b1, sp, h1b);
        __syncthreads();
        if (t == 0) { __threadfence(); g_flag[bid] = seq; }   // publish h1(s)
        phase_conv2(ts, seq, w2, b2, sp, h1b);
        __syncthreads();                      // h2 + smem reuse
        phase_conv3(s, ts, w3, b3, sp);
      }
    }
    if (work) phase_err(hs, sp);
    gbar();                                   // partials -> control

    if (bid == 0) {
      float ssum = 0.0f;
      for (int i = t; i < NWORK; i += NT) ssum += g_partial[i];
      sp[t] = ssum;
      __syncthreads();
      for (int o = 128; o > 0; o >>= 1) {
        if (t < o) sp[t] += sp[t + o];
        __syncthreads();
      }
      if (t == 0) {
        float en = sqrtf(sp[0] / (float)NY);
        float hcur = g_hs;
        int acc = (en <= 1.0f) ? 1 : 0;
        g_accept = acc;
        float tn = acc ? (g_t + hcur) : g_t;
        g_t = tn;
        float ens = fmaxf(en, 1e-8f);
        float fac = fminf(fmaxf(0.9f * powf(ens, -0.2f), 0.2f), 10.0f);
        float hn = fmaxf(hcur * fac, 1e-4f);
        g_h = hn;
        g_done = (tn >= 1.0f) ? 1 : 0;
        g_hs = fminf(hn, 1.0f - tn);
      }
    }
    gbar();                                   // control -> everyone

    if (work && *(volatile int*)&g_accept) {  // accept: y <- y5, k1 <- k7
      int base4 = bid * 2048;
      for (int q = t; q < 2048; q += NT) {
        ((float4*)g_y)[base4 + q]    = ((const float4*)g_y5)[base4 + q];
        ((float4*)g_k[0])[base4 + q] = ((const float4*)g_k[6])[base4 + q];
      }
    }
  }
  gbar();

  // ---- output head: 1x1 conv 64 -> 10 (own px)
  if (work) {
    float* ws = sp;
    float* bs = sp + 640;
    __syncthreads();
    for (int i = t; i < CC*OUTC; i += NT) ws[i] = wo[i];
    if (t < OUTC) bs[t] = bo[t];
    __syncthreads();
    if (t < 128) {
      int p = bid*128 + t;
      float accs[OUTC];
      #pragma unroll
      for (int j = 0; j < OUTC; j++) accs[j] = bs[j];
      #pragma unroll
      for (int c4 = 0; c4 < 16; c4++) {
        float4 v = *(const float4*)&g_y[(size_t)p*CC + c4*4];
        float vv[4] = {v.x, v.y, v.z, v.w};
        #pragma unroll
        for (int q = 0; q < 4; q++)
          #pragma unroll
          for (int j = 0; j < OUTC; j++)
            accs[j] = fmaf(vv[q], ws[(c4*4+q)*OUTC + j], accs[j]);
      }
      #pragma unroll
      for (int j = 0; j < OUTC; j++) out[(size_t)p*OUTC + j] = accs[j];
    }
  }
}

// ----------------------------- launcher -------------------------------------
extern "C" void kernel_launch(void* const* d_in, const int* in_sizes, int n_in,
                              void* d_out, int out_size) {
  const float* x  = (const float*)d_in[0];
  const float* w1 = (const float*)d_in[1];
  const float* b1 = (const float*)d_in[2];
  const float* w2 = (const float*)d_in[3];
  const float* b2 = (const float*)d_in[4];
  const float* w3 = (const float*)d_in[5];
  const float* b3 = (const float*)d_in[6];
  const float* wo = (const float*)d_in[7];
  const float* bo = (const float*)d_in[8];
  float* out = (float*)d_out;

  cudaFuncSetAttribute(ode_all, cudaFuncAttributeMaxDynamicSharedMemorySize,
                       SPOOL_BYTES);
  ode_all<<<GRIDN, NT, SPOOL_BYTES>>>(x, w1, b1, w2, b2, w3, b3, wo, bo, out);
}